// round 7
// baseline (speedup 1.0000x reference)
#include <cuda_runtime.h>
#include <math.h>

#define T  4
#define Bb 16
#define C  512
#define HW 256
#define Nn 256
#define C3 1536
#define HID 2048
#define NH 8
#define Dd 64
#define TB (T*Bb)            // 64
#define BN (Bb*Nn)           // 4096
#define TBN (T*Bb*Nn)        // 16384
#define PLANE (Bb*C*HW)      // 2097152
#define XSZ (T*PLANE)        // 8388608

// ---------------- scratch (no cudaMalloc allowed) ----------------
__device__ unsigned char g_s[XSZ];        // lif(x) spikes   [T,B,C,HW]
__device__ float         g_xc[XSZ];       // x + pos         [T,B,C,HW]
__device__ float         g_xt[XSZ];       // residual stream [T,B,N,C]
__device__ unsigned char g_spk1[XSZ];     // LN1 spikes      [T,B,N,C]
__device__ float         g_qkv[TBN*C3];   //                 [T,B,N,3C]
__device__ unsigned char g_qkvs[TBN*C3];  // q/k/v spikes    [T,B,N,3C]
__device__ float         g_attn[XSZ];     // attn out        [T,B,N,C]
__device__ unsigned char g_aspk[XSZ];
__device__ unsigned char g_spk2[XSZ];     // LN2 spikes
__device__ float g_qkv_wt[C*C3];          // [cin][cout]
__device__ float g_proj_wt[C*C];
__device__ float g_fc1_wt[C*HID];
__device__ float g_fc2_wt[HID*C];

__device__ __forceinline__ float sigm(float w){ return 1.f/(1.f+expf(-w)); }

// ---------------- weight transposes (run every launch, deterministic) ----
__global__ void k_wt(const float* __restrict__ src, int nR, int nC, int mode){
    int idx = blockIdx.x*256 + threadIdx.x;
    if (idx >= nR*nC) return;
    int r = idx / nC, c = idx % nC;
    float v = src[idx];
    float* dst = (mode==0)? g_qkv_wt : (mode==1)? g_proj_wt : (mode==2)? g_fc1_wt : g_fc2_wt;
    dst[(size_t)c*nR + r] = v;
}

// ---------------- generic LIF over leading T axis, spike output ----------
__global__ void k_lif_time(const float* __restrict__ src, unsigned char* __restrict__ dst,
                           int X, const float* __restrict__ lifw, int li){
    int idx = blockIdx.x*256 + threadIdx.x;
    if (idx >= X) return;
    float decay = sigm(lifw[li]);
    float v = 0.f;
    for (int t=0; t<T; t++){
        size_t id = (size_t)t*X + idx;
        float x = src[id];
        v = v + (x - v)*decay;
        unsigned char s = (v >= 1.0f);
        if (s) v = 0.f;
        dst[id] = s;
    }
}

// ---------------- depthwise 3x3 conv on spikes + residual ----------------
__global__ void k_conv(const float* __restrict__ x, const float* __restrict__ conv_w,
                       const float* __restrict__ conv_b){
    __shared__ float tile[18*18];
    int tbc = blockIdx.x;                 // (tb*C + c)
    int c = tbc & (C-1);
    size_t base = (size_t)tbc*HW;
    int tid = threadIdx.x;
    for (int i = tid; i < 324; i += 256){
        int y = i/18 - 1, xx = i%18 - 1;
        float v = 0.f;
        if (y>=0 && y<16 && xx>=0 && xx<16) v = (float)g_s[base + y*16 + xx];
        tile[i] = v;
    }
    __syncthreads();
    int py = tid >> 4, px = tid & 15;
    float acc = 0.f;
    #pragma unroll
    for (int ky=0; ky<3; ky++)
        #pragma unroll
        for (int kx=0; kx<3; kx++)
            acc += tile[(py+ky)*18 + px+kx] * conv_w[c*9 + ky*3 + kx];
    g_xc[base + tid] = x[base + tid] + acc + conv_b[c];
}

// ---------------- batched 2D transpose (per z-slice) ---------------------
__global__ void k_tr(const float* __restrict__ src, float* __restrict__ dst,
                     int rows, int cols){
    __shared__ float tile[32][33];
    int z = blockIdx.z;
    const float* s = src + (size_t)z*rows*cols;
    float*       d = dst + (size_t)z*rows*cols;
    int xx = blockIdx.x*32 + threadIdx.x;
    int yy = blockIdx.y*32 + threadIdx.y;
    tile[threadIdx.y][threadIdx.x] = s[(size_t)yy*cols + xx];
    __syncthreads();
    int x2 = blockIdx.y*32 + threadIdx.x;   // index within 'rows'
    int y2 = blockIdx.x*32 + threadIdx.y;   // index within 'cols'
    d[(size_t)y2*rows + x2] = tile[threadIdx.x][threadIdx.y];
}

// ---------------- block-wide sum with broadcast --------------------------
__device__ __forceinline__ float blockSum(float v, float* red){
    #pragma unroll
    for (int off=16; off; off>>=1) v += __shfl_down_sync(0xffffffffu, v, off);
    int lane = threadIdx.x & 31, w = threadIdx.x >> 5;
    if (lane==0) red[w] = v;
    __syncthreads();
    if (w==0){
        float s = (lane < 8) ? red[lane] : 0.f;
        #pragma unroll
        for (int off=4; off; off>>=1) s += __shfl_down_sync(0xffffffffu, s, off);
        if (lane==0) red[8] = s;
    }
    __syncthreads();
    float r = red[8];
    __syncthreads();
    return r;
}

// ---------------- LayerNorm + LIF -> spikes ------------------------------
__global__ void k_ln_lif(const float* __restrict__ gam, const float* __restrict__ bet,
                         const float* __restrict__ lifw, int li,
                         unsigned char* __restrict__ spk){
    __shared__ float red[9];
    int bn = blockIdx.x;  int b = bn >> 8;  int n = bn & 255;
    int tid = threadIdx.x;
    float decay = sigm(lifw[li]);
    float g0 = gam[tid], g1 = gam[tid+256];
    float b0 = bet[tid], b1 = bet[tid+256];
    float v0 = 0.f, v1 = 0.f;
    for (int t=0; t<T; t++){
        int tok = (t*Bb + b)*Nn + n;
        const float* row = g_xt + (size_t)tok*C;
        float x0 = row[tid], x1 = row[tid+256];
        float m  = blockSum(x0+x1, red) * (1.f/512.f);
        float d0 = x0-m, d1 = x1-m;
        float var = blockSum(d0*d0 + d1*d1, red) * (1.f/512.f);
        float inv = 1.f / sqrtf(var + 1e-5f);
        float y0 = d0*inv*g0 + b0;
        float y1 = d1*inv*g1 + b1;
        v0 = v0 + (y0 - v0)*decay;
        v1 = v1 + (y1 - v1)*decay;
        unsigned char s0 = (v0 >= 1.0f); if (s0) v0 = 0.f;
        unsigned char s1 = (v1 >= 1.0f); if (s1) v1 = 0.f;
        spk[(size_t)tok*C + tid]       = s0;
        spk[(size_t)tok*C + tid + 256] = s1;
    }
}

// ---------------- sparse gather: spikes @ qkv_w^T ------------------------
__global__ void k_gather_qkv(){
    __shared__ unsigned int srow4[C/4];
    unsigned char* srow = (unsigned char*)srow4;
    int tok = blockIdx.x, tid = threadIdx.x;
    srow[tid]     = g_spk1[(size_t)tok*C + tid];
    srow[tid+256] = g_spk1[(size_t)tok*C + tid + 256];
    __syncthreads();
    float a0=0,a1=0,a2=0,a3=0,a4=0,a5=0;
    for (int w=0; w<C/4; w++){
        unsigned int wv = srow4[w];
        if (!wv) continue;
        #pragma unroll
        for (int bt=0; bt<4; bt++){
            if ((wv >> (8*bt)) & 0xFFu){
                int c = w*4 + bt;
                const float* wr = g_qkv_wt + (size_t)c*C3;
                a0 += wr[tid];       a1 += wr[tid+256];  a2 += wr[tid+512];
                a3 += wr[tid+768];   a4 += wr[tid+1024]; a5 += wr[tid+1280];
            }
        }
    }
    float* o = g_qkv + (size_t)tok*C3;
    o[tid]=a0; o[tid+256]=a1; o[tid+512]=a2; o[tid+768]=a3; o[tid+1024]=a4; o[tid+1280]=a5;
}

// ---------------- LIF over T for q/k/v (per-slice decay) -----------------
__global__ void k_lif_qkv(const float* __restrict__ lifw){
    int idx = blockIdx.x*256 + threadIdx.x;     // over BN*C3
    if (idx >= BN*C3) return;
    int cc = idx % C3;
    float decay = sigm(lifw[2 + cc/C]);
    float v = 0.f;
    for (int t=0; t<T; t++){
        size_t id = (size_t)t*BN*C3 + idx;
        float x = g_qkv[id];
        v = v + (x - v)*decay;
        unsigned char s = (v >= 1.0f);
        if (s) v = 0.f;
        g_qkvs[id] = s;
    }
}

// ---------------- exact integer linear attention -------------------------
__global__ void k_attn(){
    __shared__ unsigned int kcol[Dd][8];
    __shared__ unsigned int vcol[Dd][8];
    __shared__ int kvs[Dd*Dd];
    int bx = blockIdx.x;
    int hd = bx & 7; int b = (bx >> 3) & 15; int t = bx >> 7;
    int tid = threadIdx.x;
    int tbase = (t*Bb + b)*Nn;
    int koff = C  + hd*Dd;
    int voff = 2*C + hd*Dd;
    for (int s = tid; s < Dd*8; s += 256){
        int e = s >> 3, w = s & 7;
        unsigned int kb = 0, vb = 0;
        for (int i=0; i<32; i++){
            int n = w*32 + i;
            size_t base = (size_t)(tbase + n)*C3;
            kb |= ((unsigned int)(g_qkvs[base + koff + e] != 0)) << i;
            vb |= ((unsigned int)(g_qkvs[base + voff + e] != 0)) << i;
        }
        kcol[e][w] = kb; vcol[e][w] = vb;
    }
    __syncthreads();
    for (int s = tid; s < Dd*Dd; s += 256){
        int e = s >> 6, f = s & 63;
        int sum = 0;
        #pragma unroll
        for (int w=0; w<8; w++) sum += __popc(kcol[e][w] & vcol[f][w]);
        kvs[s] = sum;
    }
    __syncthreads();
    int n = tid;
    const unsigned char* qr = g_qkvs + (size_t)(tbase + n)*C3 + hd*Dd;
    unsigned int qb0=0, qb1=0;
    for (int i=0; i<32; i++){
        qb0 |= ((unsigned int)(qr[i]    != 0)) << i;
        qb1 |= ((unsigned int)(qr[32+i] != 0)) << i;
    }
    int acc[Dd];
    #pragma unroll
    for (int f=0; f<Dd; f++) acc[f] = 0;
    unsigned int m = qb0;
    while (m){
        int e = __ffs(m)-1; m &= m-1;
        const int* kr = kvs + e*Dd;
        #pragma unroll
        for (int f=0; f<Dd; f++) acc[f] += kr[f];
    }
    m = qb1;
    while (m){
        int e = __ffs(m)+31; m &= m-1;
        const int* kr = kvs + e*Dd;
        #pragma unroll
        for (int f=0; f<Dd; f++) acc[f] += kr[f];
    }
    float* outp = g_attn + (size_t)(tbase + n)*C + hd*Dd;
    #pragma unroll
    for (int f=0; f<Dd; f++) outp[f] = (float)acc[f] * 0.125f;
}

// ---------------- sparse gather: a_spk @ proj_w^T + bias + residual ------
__global__ void k_proj(const float* __restrict__ proj_b){
    __shared__ unsigned int srow4[C/4];
    unsigned char* srow = (unsigned char*)srow4;
    int tok = blockIdx.x, tid = threadIdx.x;
    srow[tid]     = g_aspk[(size_t)tok*C + tid];
    srow[tid+256] = g_aspk[(size_t)tok*C + tid + 256];
    __syncthreads();
    float a0 = 0.f, a1 = 0.f;
    for (int w=0; w<C/4; w++){
        unsigned int wv = srow4[w];
        if (!wv) continue;
        #pragma unroll
        for (int bt=0; bt<4; bt++){
            if ((wv >> (8*bt)) & 0xFFu){
                int c = w*4 + bt;
                const float* wr = g_proj_wt + (size_t)c*C;
                a0 += wr[tid]; a1 += wr[tid+256];
            }
        }
    }
    a0 += proj_b[tid]; a1 += proj_b[tid+256];
    g_xt[(size_t)tok*C + tid]       += a0;
    g_xt[(size_t)tok*C + tid + 256] += a1;
}

// ---------------- fused MLP: fc1 gather -> LIF -> fc2 gather -> residual -
__global__ void k_mlp(const float* __restrict__ lifw, const float* __restrict__ fc1_b,
                      const float* __restrict__ fc2_b){
    __shared__ unsigned int srow4[C/4];
    __shared__ unsigned char hs[HID];
    __shared__ int hlist[T*HID];
    __shared__ int hcnt;
    unsigned char* srow = (unsigned char*)srow4;
    int bn = blockIdx.x; int b = bn >> 8; int n = bn & 255;
    int tid = threadIdx.x;
    float decay = sigm(lifw[7]);
    if (tid == 0) hcnt = 0;
    float v[8];
    #pragma unroll
    for (int k=0; k<8; k++) v[k] = 0.f;
    for (int t=0; t<T; t++){
        int tok = (t*Bb + b)*Nn + n;
        srow[tid]     = g_spk2[(size_t)tok*C + tid];
        srow[tid+256] = g_spk2[(size_t)tok*C + tid + 256];
        __syncthreads();
        float cur[8];
        #pragma unroll
        for (int k=0; k<8; k++) cur[k] = 0.f;
        for (int w=0; w<C/4; w++){
            unsigned int wv = srow4[w];
            if (!wv) continue;
            #pragma unroll
            for (int bt=0; bt<4; bt++){
                if ((wv >> (8*bt)) & 0xFFu){
                    int c = w*4 + bt;
                    const float* wr = g_fc1_wt + (size_t)c*HID;
                    #pragma unroll
                    for (int k=0; k<8; k++) cur[k] += wr[tid + (k<<8)];
                }
            }
        }
        #pragma unroll
        for (int k=0; k<8; k++){
            cur[k] += fc1_b[tid + (k<<8)];
            v[k] = v[k] + (cur[k] - v[k])*decay;
            unsigned char s = (v[k] >= 1.0f);
            hs[tid + (k<<8)] = s;
            if (s) v[k] = 0.f;
        }
        __syncthreads();
        if (tid < 32){               // warp 0 builds ordered (t,j) list — deterministic
            int lane = tid;
            for (int bj=0; bj<HID; bj+=32){
                int pred = hs[bj + lane];
                unsigned int bm = __ballot_sync(0xffffffffu, pred != 0);
                int cbase = hcnt;
                __syncwarp();
                int pre = __popc(bm & ((1u << lane) - 1u));
                if (pred) hlist[cbase + pre] = t*HID + bj + lane;
                if (lane == 0) hcnt = cbase + __popc(bm);
                __syncwarp();
            }
        }
        __syncthreads();
    }
    int cnt = hcnt;
    float o00=0,o01=0,o10=0,o11=0,o20=0,o21=0,o30=0,o31=0;
    for (int i=0; i<cnt; i++){
        int ent = hlist[i];
        int te = ent >> 11; int j = ent & (HID-1);
        const float* wr = g_fc2_wt + (size_t)j*C;
        float w0 = wr[tid], w1 = wr[tid+256];
        if      (te == 0){ o00 += w0; o01 += w1; }
        else if (te == 1){ o10 += w0; o11 += w1; }
        else if (te == 2){ o20 += w0; o21 += w1; }
        else             { o30 += w0; o31 += w1; }
    }
    float bb0 = fc2_b[tid], bb1 = fc2_b[tid+256];
    {
        int tok = (0*Bb + b)*Nn + n;
        g_xt[(size_t)tok*C + tid]     += o00 + bb0;
        g_xt[(size_t)tok*C + tid+256] += o01 + bb1;
    }
    {
        int tok = (1*Bb + b)*Nn + n;
        g_xt[(size_t)tok*C + tid]     += o10 + bb0;
        g_xt[(size_t)tok*C + tid+256] += o11 + bb1;
    }
    {
        int tok = (2*Bb + b)*Nn + n;
        g_xt[(size_t)tok*C + tid]     += o20 + bb0;
        g_xt[(size_t)tok*C + tid+256] += o21 + bb1;
    }
    {
        int tok = (3*Bb + b)*Nn + n;
        g_xt[(size_t)tok*C + tid]     += o30 + bb0;
        g_xt[(size_t)tok*C + tid+256] += o31 + bb1;
    }
}

// ------------------------------- launch ----------------------------------
extern "C" void kernel_launch(void* const* d_in, const int* in_sizes, int n_in,
                              void* d_out, int out_size){
    const float* x      = (const float*)d_in[0];
    const float* conv_w = (const float*)d_in[1];
    const float* conv_b = (const float*)d_in[2];
    const float* ln1_g  = (const float*)d_in[3];
    const float* ln1_b  = (const float*)d_in[4];
    const float* qkv_w  = (const float*)d_in[5];
    const float* proj_w = (const float*)d_in[6];
    const float* proj_b = (const float*)d_in[7];
    const float* ln2_g  = (const float*)d_in[8];
    const float* ln2_b  = (const float*)d_in[9];
    const float* fc1_w  = (const float*)d_in[10];
    const float* fc1_b  = (const float*)d_in[11];
    const float* fc2_w  = (const float*)d_in[12];
    const float* fc2_b  = (const float*)d_in[13];
    const float* lifw   = (const float*)d_in[14];
    float* out = (float*)d_out;

    unsigned char *p_s, *p_spk1, *p_spk2, *p_aspk;
    float *p_xc, *p_xt, *p_attn;
    cudaGetSymbolAddress((void**)&p_s,    g_s);
    cudaGetSymbolAddress((void**)&p_xc,   g_xc);
    cudaGetSymbolAddress((void**)&p_xt,   g_xt);
    cudaGetSymbolAddress((void**)&p_spk1, g_spk1);
    cudaGetSymbolAddress((void**)&p_spk2, g_spk2);
    cudaGetSymbolAddress((void**)&p_attn, g_attn);
    cudaGetSymbolAddress((void**)&p_aspk, g_aspk);

    // weight transposes
    k_wt<<<(C3*C + 255)/256, 256>>>(qkv_w, C3, C, 0);
    k_wt<<<(C*C  + 255)/256, 256>>>(proj_w, C, C, 1);
    k_wt<<<(HID*C + 255)/256, 256>>>(fc1_w, HID, C, 2);
    k_wt<<<(C*HID + 255)/256, 256>>>(fc2_w, C, HID, 3);

    // 1) lif(x) spikes
    k_lif_time<<<PLANE/256, 256>>>(x, p_s, PLANE, lifw, 0);
    // 2) depthwise conv pos-emb + residual
    k_conv<<<TB*C, 256>>>(x, conv_w, conv_b);
    // 3) [C,HW] -> [N,C] token layout
    k_tr<<<dim3(Nn/32, C/32, TB), dim3(32,32)>>>(p_xc, p_xt, C, Nn);
    // 4) LN1 + LIF
    k_ln_lif<<<BN, 256>>>(ln1_g, ln1_b, lifw, 1, p_spk1);
    // 5) qkv sparse gather
    k_gather_qkv<<<TBN, 256>>>();
    // 6) q/k/v LIF
    k_lif_qkv<<<(BN*C3)/256, 256>>>(lifw);
    // 7) linear attention (exact integer)
    k_attn<<<T*Bb*NH, 256>>>();
    // 8) attn LIF
    k_lif_time<<<(BN*C)/256, 256>>>(p_attn, p_aspk, BN*C, lifw, 5);
    // 9) proj gather + residual
    k_proj<<<TBN, 256>>>(proj_b);
    // 10) LN2 + LIF
    k_ln_lif<<<BN, 256>>>(ln2_g, ln2_b, lifw, 6, p_spk2);
    // 11) fused MLP + residual
    k_mlp<<<BN, 256>>>(lifw, fc1_b, fc2_b);
    // 12) [N,C] -> [C,HW] output layout
    k_tr<<<dim3(C/32, Nn/32, TB), dim3(32,32)>>>(p_xt, out, Nn, C);
}

// round 10
// speedup vs baseline: 1.5197x; 1.5197x over previous
#include <cuda_runtime.h>
#include <cuda_bf16.h>
#include <math.h>

#define T  4
#define Bb 16
#define C  512
#define HW 256
#define Nn 256
#define C3 1536
#define HID 2048
#define NH 8
#define Dd 64
#define TB (T*Bb)            // 64
#define BN (Bb*Nn)           // 4096
#define TBN (T*Bb*Nn)        // 16384
#define XSZ (T*Bb*C*HW)      // 8388608

// ---------------- scratch (no cudaMalloc allowed) ----------------
__device__ float         g_xc[XSZ];       // x + pos         [T,B,C,HW]
__device__ float         g_xt[XSZ];       // residual stream [T,B,N,C]
__device__ unsigned char g_qkvs[TBN*C3];  // q/k/v spikes    [T,B,N,3C]
__device__ float         g_attn[XSZ];     // attn out        [T,B,N,C]
__device__ __align__(16) __nv_bfloat16 g_wq [C*C3];   // [cin][3C]
__device__ __align__(16) __nv_bfloat16 g_wp [C*C];    // [cin][C]
__device__ __align__(16) __nv_bfloat16 g_wf1[C*HID];  // [cin][HID]
__device__ __align__(16) __nv_bfloat16 g_wf2[HID*C];  // [hid][C]

__device__ __forceinline__ float sigm(float w){ return 1.f/(1.f+expf(-w)); }

// ---------- tiled transpose fp32 -> bf16 : src[nR][nC] -> dst[nC][nR] ----
__global__ void k_wt(const float* __restrict__ src, __nv_bfloat16* __restrict__ dst,
                     int nR, int nC){
    __shared__ float tile[32][33];
    int cx = blockIdx.x*32 + threadIdx.x;
    int ry = blockIdx.y*32 + threadIdx.y;
    tile[threadIdx.y][threadIdx.x] = src[(size_t)ry*nC + cx];
    __syncthreads();
    int ox = blockIdx.y*32 + threadIdx.x;   // within nR
    int oy = blockIdx.x*32 + threadIdx.y;   // within nC
    dst[(size_t)oy*nR + ox] = __float2bfloat16(tile[threadIdx.x][threadIdx.y]);
}

// ---------- fused lif(x) + depthwise 3x3 conv + residual -----------------
__global__ void k_convf(const float* __restrict__ x, const float* __restrict__ conv_w,
                        const float* __restrict__ conv_b, const float* __restrict__ lifw,
                        float* __restrict__ xc){
    __shared__ float xs[T][324];
    __shared__ unsigned char ss[T][324];
    int bc = blockIdx.x;  int b = bc >> 9;  int c = bc & 511;
    int tid = threadIdx.x;
    float decay = sigm(lifw[0]);
    for (int i = tid; i < 324; i += 256){
        int y = i/18 - 1, xx = i%18 - 1;
        bool in = (y>=0 && y<16 && xx>=0 && xx<16);
        int p = y*16 + xx;
        #pragma unroll
        for (int t=0; t<T; t++)
            xs[t][i] = in ? x[((size_t)(t*Bb+b)*C + c)*HW + p] : 0.f;
    }
    __syncthreads();
    for (int i = tid; i < 324; i += 256){
        float v = 0.f;
        #pragma unroll
        for (int t=0; t<T; t++){
            float xv = xs[t][i];
            v = v + (xv - v)*decay;
            unsigned char s = (v >= 1.0f);
            if (s) v = 0.f;
            ss[t][i] = s;
        }
    }
    __syncthreads();
    int py = tid >> 4, px = tid & 15;
    float w[9];
    #pragma unroll
    for (int j=0;j<9;j++) w[j] = conv_w[c*9 + j];
    float cb = conv_b[c];
    #pragma unroll
    for (int t=0; t<T; t++){
        float acc = 0.f;
        #pragma unroll
        for (int ky=0; ky<3; ky++)
            #pragma unroll
            for (int kx=0; kx<3; kx++)
                acc += (float)ss[t][(py+ky)*18 + px+kx] * w[ky*3+kx];
        xc[((size_t)(t*Bb+b)*C + c)*HW + tid] = xs[t][(py+1)*18 + px+1] + acc + cb;
    }
}

// ---------- batched 2D fp32 transpose (per z-slice) ----------------------
__global__ void k_tr(const float* __restrict__ src, float* __restrict__ dst,
                     int rows, int cols){
    __shared__ float tile[32][33];
    int z = blockIdx.z;
    const float* s = src + (size_t)z*rows*cols;
    float*       d = dst + (size_t)z*rows*cols;
    int xx = blockIdx.x*32 + threadIdx.x;
    int yy = blockIdx.y*32 + threadIdx.y;
    tile[threadIdx.y][threadIdx.x] = s[(size_t)yy*cols + xx];
    __syncthreads();
    int x2 = blockIdx.y*32 + threadIdx.x;
    int y2 = blockIdx.x*32 + threadIdx.y;
    d[(size_t)y2*rows + x2] = tile[threadIdx.x][threadIdx.y];
}

// ---------- block-wide sum over 512 threads ------------------------------
__device__ __forceinline__ float bsum(float v, float* red){
    #pragma unroll
    for (int off=16; off; off>>=1) v += __shfl_down_sync(0xffffffffu, v, off);
    int lane = threadIdx.x & 31, w = threadIdx.x >> 5;
    if (lane==0) red[w] = v;
    __syncthreads();
    if (w==0){
        float s = (lane < 16) ? red[lane] : 0.f;
        #pragma unroll
        for (int off=8; off; off>>=1) s += __shfl_down_sync(0xffffffffu, s, off);
        if (lane==0) red[16] = s;
    }
    __syncthreads();
    float r = red[16];
    __syncthreads();
    return r;
}

// ---------- fused LN1 + LIF + qkv sparse gather (bf16) + qkv LIF ---------
__global__ void __launch_bounds__(512) k_qkv(
        const float* __restrict__ ln1_g, const float* __restrict__ ln1_b,
        const float* __restrict__ lifw,  const float* __restrict__ xt,
        unsigned char* __restrict__ qkvs){
    __shared__ unsigned int mask[16];
    __shared__ float red[17];
    int bn = blockIdx.x;  int b = bn >> 8;  int n = bn & 255;
    int tid = threadIdx.x;
    float gg = ln1_g[tid], be = ln1_b[tid];
    float d1 = sigm(lifw[1]);
    float dq = sigm(lifw[2 + ((tid < 384) ? (tid >> 7) : 0)]);
    float vln = 0.f;
    float v0=0.f, v1=0.f, v2=0.f, v3=0.f;
    const uint2* wq2 = (const uint2*)g_wq;
    for (int t=0; t<T; t++){
        int tok = (t*Bb + b)*Nn + n;
        float xv = xt[(size_t)tok*C + tid];
        float m  = bsum(xv, red) * (1.f/512.f);
        float d  = xv - m;
        float var = bsum(d*d, red) * (1.f/512.f);
        float y = d * (1.f/sqrtf(var + 1e-5f)) * gg + be;
        vln = vln + (y - vln)*d1;
        int s = (vln >= 1.0f); if (s) vln = 0.f;
        unsigned bm = __ballot_sync(0xffffffffu, s);
        if ((tid & 31) == 0) mask[tid >> 5] = bm;
        __syncthreads();
        if (tid < 384){
            float a0=0.f, a1=0.f, a2=0.f, a3=0.f;
            #pragma unroll 1
            for (int w=0; w<16; w++){
                unsigned mv = mask[w];
                while (mv){
                    int c = w*32 + __ffs(mv) - 1;  mv &= mv - 1;
                    uint2 pv = wq2[c*384 + tid];
                    __nv_bfloat162 p0 = *reinterpret_cast<__nv_bfloat162*>(&pv.x);
                    __nv_bfloat162 p1 = *reinterpret_cast<__nv_bfloat162*>(&pv.y);
                    float2 f0 = __bfloat1622float2(p0);
                    float2 f1 = __bfloat1622float2(p1);
                    a0 += f0.x; a1 += f0.y; a2 += f1.x; a3 += f1.y;
                }
            }
            v0 = v0 + (a0 - v0)*dq;  v1 = v1 + (a1 - v1)*dq;
            v2 = v2 + (a2 - v2)*dq;  v3 = v3 + (a3 - v3)*dq;
            uchar4 sc;
            sc.x = (v0 >= 1.0f); if (sc.x) v0 = 0.f;
            sc.y = (v1 >= 1.0f); if (sc.y) v1 = 0.f;
            sc.z = (v2 >= 1.0f); if (sc.z) v2 = 0.f;
            sc.w = (v3 >= 1.0f); if (sc.w) v3 = 0.f;
            *reinterpret_cast<uchar4*>(qkvs + (size_t)tok*C3 + tid*4) = sc;
        }
        __syncthreads();
    }
}

// ---------- exact integer linear attention (smem-staged loads) -----------
__global__ void k_attn(const unsigned char* __restrict__ qkvs, float* __restrict__ attn){
    __shared__ int4 stage[1024];            // 256 tokens x 64B
    __shared__ unsigned int kcol[Dd][8];
    __shared__ unsigned int vcol[Dd][8];
    __shared__ int kvs[Dd*Dd];
    int bx = blockIdx.x;
    int hd = bx & 7;  int b = (bx >> 3) & 15;  int t = bx >> 7;
    int tid = threadIdx.x;
    int tbase = (t*Bb + b)*Nn;
    const unsigned char* base = qkvs + (size_t)tbase*C3;
    const unsigned char* sb = (const unsigned char*)stage;
    int koff = C + hd*Dd, voff = 2*C + hd*Dd, qoff = hd*Dd;

    for (int i=tid; i<1024; i+=256){
        int nn = i >> 2, ch = i & 3;
        stage[i] = *reinterpret_cast<const int4*>(base + (size_t)nn*C3 + koff + ch*16);
    }
    __syncthreads();
    for (int s=tid; s<512; s+=256){
        int e = s >> 3, w = s & 7;
        unsigned kb = 0;
        #pragma unroll 4
        for (int i=0;i<32;i++) kb |= ((unsigned)(sb[(w*32+i)*64 + e] != 0)) << i;
        kcol[e][w] = kb;
    }
    __syncthreads();
    for (int i=tid; i<1024; i+=256){
        int nn = i >> 2, ch = i & 3;
        stage[i] = *reinterpret_cast<const int4*>(base + (size_t)nn*C3 + voff + ch*16);
    }
    __syncthreads();
    for (int s=tid; s<512; s+=256){
        int e = s >> 3, w = s & 7;
        unsigned vb = 0;
        #pragma unroll 4
        for (int i=0;i<32;i++) vb |= ((unsigned)(sb[(w*32+i)*64 + e] != 0)) << i;
        vcol[e][w] = vb;
    }
    __syncthreads();
    for (int s=tid; s<Dd*Dd; s+=256){
        int e = s >> 6, f = s & 63;
        int sum = 0;
        #pragma unroll
        for (int w=0; w<8; w++) sum += __popc(kcol[e][w] & vcol[f][w]);
        kvs[s] = sum;
    }
    __syncthreads();
    for (int i=tid; i<1024; i+=256){
        int nn = i >> 2, ch = i & 3;
        stage[i] = *reinterpret_cast<const int4*>(base + (size_t)nn*C3 + qoff + ch*16);
    }
    __syncthreads();
    int n = tid;
    unsigned qb0=0, qb1=0;
    #pragma unroll 4
    for (int i=0;i<32;i++){
        qb0 |= ((unsigned)(sb[n*64 + i]      != 0)) << i;
        qb1 |= ((unsigned)(sb[n*64 + 32 + i] != 0)) << i;
    }
    int acc[Dd];
    #pragma unroll
    for (int f=0; f<Dd; f++) acc[f] = 0;
    unsigned m = qb0;
    while (m){
        int e = __ffs(m) - 1;  m &= m - 1;
        const int* kr = kvs + e*Dd;
        #pragma unroll
        for (int f=0; f<Dd; f++) acc[f] += kr[f];
    }
    m = qb1;
    while (m){
        int e = __ffs(m) + 31;  m &= m - 1;
        const int* kr = kvs + e*Dd;
        #pragma unroll
        for (int f=0; f<Dd; f++) acc[f] += kr[f];
    }
    float* outp = attn + (size_t)(tbase + n)*C + hd*Dd;
    #pragma unroll
    for (int f=0; f<Dd; f++) outp[f] = (float)acc[f] * 0.125f;
}

// ---------- fused attn LIF + proj gather (bf16) + residual ---------------
__global__ void __launch_bounds__(512) k_projf(
        const float* __restrict__ lifw, const float* __restrict__ proj_b,
        const float* __restrict__ attn, float* __restrict__ xt){
    __shared__ unsigned int mask[16];
    int bn = blockIdx.x;  int b = bn >> 8;  int n = bn & 255;
    int tid = threadIdx.x;
    float dec = sigm(lifw[5]);
    float pb = proj_b[tid];
    float v = 0.f;
    for (int t=0; t<T; t++){
        int tok = (t*Bb + b)*Nn + n;
        float a = attn[(size_t)tok*C + tid];
        v = v + (a - v)*dec;
        int s = (v >= 1.0f); if (s) v = 0.f;
        unsigned bm = __ballot_sync(0xffffffffu, s);
        if ((tid & 31) == 0) mask[tid >> 5] = bm;
        __syncthreads();
        float o = 0.f;
        #pragma unroll 1
        for (int w=0; w<16; w++){
            unsigned mv = mask[w];
            while (mv){
                int c = w*32 + __ffs(mv) - 1;  mv &= mv - 1;
                o += __bfloat162float(g_wp[(size_t)c*C + tid]);
            }
        }
        xt[(size_t)tok*C + tid] += o + pb;
        __syncthreads();
    }
}

// ---------- fused LN2 + LIF + fc1 gather + hidden LIF + fc2 + residual ---
__global__ void __launch_bounds__(512) k_mlp(
        const float* __restrict__ lifw,
        const float* __restrict__ ln2_g, const float* __restrict__ ln2_b,
        const float* __restrict__ fc1_b, const float* __restrict__ fc2_b,
        float* __restrict__ xt){
    __shared__ unsigned int mask[16];
    __shared__ float red[17];
    __shared__ unsigned char hs[HID];
    __shared__ int hlist[HID];
    __shared__ int hcnt;
    int bn = blockIdx.x;  int b = bn >> 8;  int n = bn & 255;
    int tid = threadIdx.x;
    int lane = tid & 31;
    float gg = ln2_g[tid], be = ln2_b[tid];
    float d6 = sigm(lifw[6]), d7 = sigm(lifw[7]);
    float fb0 = fc1_b[tid*4], fb1 = fc1_b[tid*4+1], fb2 = fc1_b[tid*4+2], fb3 = fc1_b[tid*4+3];
    float f2b = fc2_b[tid];
    float vln = 0.f;
    float v0=0.f, v1=0.f, v2=0.f, v3=0.f;
    const uint2* w1 = (const uint2*)g_wf1;
    for (int t=0; t<T; t++){
        int tok = (t*Bb + b)*Nn + n;
        float xv = xt[(size_t)tok*C + tid];
        float m  = bsum(xv, red) * (1.f/512.f);
        float d  = xv - m;
        float var = bsum(d*d, red) * (1.f/512.f);
        float y = d * (1.f/sqrtf(var + 1e-5f)) * gg + be;
        vln = vln + (y - vln)*d6;
        int s = (vln >= 1.0f); if (s) vln = 0.f;
        unsigned bm = __ballot_sync(0xffffffffu, s);
        if (lane == 0) mask[tid >> 5] = bm;
        __syncthreads();
        float a0=0.f, a1=0.f, a2=0.f, a3=0.f;
        #pragma unroll 1
        for (int w=0; w<16; w++){
            unsigned mv = mask[w];
            while (mv){
                int c = w*32 + __ffs(mv) - 1;  mv &= mv - 1;
                uint2 pv = w1[c*512 + tid];
                __nv_bfloat162 p0 = *reinterpret_cast<__nv_bfloat162*>(&pv.x);
                __nv_bfloat162 p1 = *reinterpret_cast<__nv_bfloat162*>(&pv.y);
                float2 f0 = __bfloat1622float2(p0);
                float2 f1 = __bfloat1622float2(p1);
                a0 += f0.x; a1 += f0.y; a2 += f1.x; a3 += f1.y;
            }
        }
        a0 += fb0; a1 += fb1; a2 += fb2; a3 += fb3;
        v0 = v0 + (a0 - v0)*d7;  v1 = v1 + (a1 - v1)*d7;
        v2 = v2 + (a2 - v2)*d7;  v3 = v3 + (a3 - v3)*d7;
        unsigned char s0 = (v0 >= 1.0f); if (s0) v0 = 0.f;
        unsigned char s1 = (v1 >= 1.0f); if (s1) v1 = 0.f;
        unsigned char s2 = (v2 >= 1.0f); if (s2) v2 = 0.f;
        unsigned char s3 = (v3 >= 1.0f); if (s3) v3 = 0.f;
        hs[tid*4]   = s0;  hs[tid*4+1] = s1;
        hs[tid*4+2] = s2;  hs[tid*4+3] = s3;
        if (tid == 0) hcnt = 0;
        __syncthreads();
        if (tid < 32){
            for (int bj=0; bj<HID; bj+=32){
                int pred = hs[bj + lane];
                unsigned bm2 = __ballot_sync(0xffffffffu, pred != 0);
                int cb = hcnt;
                __syncwarp();
                int pre = __popc(bm2 & ((1u << lane) - 1u));
                if (pred) hlist[cb + pre] = bj + lane;
                if (lane == 0) hcnt = cb + __popc(bm2);
                __syncwarp();
            }
        }
        __syncthreads();
        float o = 0.f;
        int cnt = hcnt;
        for (int i=0; i<cnt; i++)
            o += __bfloat162float(g_wf2[(size_t)hlist[i]*C + tid]);
        xt[(size_t)tok*C + tid] += o + f2b;
        __syncthreads();
    }
}

// ------------------------------- launch ----------------------------------
extern "C" void kernel_launch(void* const* d_in, const int* in_sizes, int n_in,
                              void* d_out, int out_size){
    const float* x      = (const float*)d_in[0];
    const float* conv_w = (const float*)d_in[1];
    const float* conv_b = (const float*)d_in[2];
    const float* ln1_g  = (const float*)d_in[3];
    const float* ln1_b  = (const float*)d_in[4];
    const float* qkv_w  = (const float*)d_in[5];
    const float* proj_w = (const float*)d_in[6];
    const float* proj_b = (const float*)d_in[7];
    const float* ln2_g  = (const float*)d_in[8];
    const float* ln2_b  = (const float*)d_in[9];
    const float* fc1_w  = (const float*)d_in[10];
    const float* fc1_b  = (const float*)d_in[11];
    const float* fc2_w  = (const float*)d_in[12];
    const float* fc2_b  = (const float*)d_in[13];
    const float* lifw   = (const float*)d_in[14];
    float* out = (float*)d_out;

    float *p_xc, *p_xt, *p_attn;
    unsigned char* p_qkvs;
    __nv_bfloat16 *p_wq, *p_wp, *p_wf1, *p_wf2;
    cudaGetSymbolAddress((void**)&p_xc,   g_xc);
    cudaGetSymbolAddress((void**)&p_xt,   g_xt);
    cudaGetSymbolAddress((void**)&p_attn, g_attn);
    cudaGetSymbolAddress((void**)&p_qkvs, g_qkvs);
    cudaGetSymbolAddress((void**)&p_wq,   g_wq);
    cudaGetSymbolAddress((void**)&p_wp,   g_wp);
    cudaGetSymbolAddress((void**)&p_wf1,  g_wf1);
    cudaGetSymbolAddress((void**)&p_wf2,  g_wf2);

    dim3 tb32(32,32);
    // weight transposes -> bf16
    k_wt<<<dim3(512/32, 1536/32), tb32>>>(qkv_w,  p_wq, 1536, 512);
    k_wt<<<dim3(512/32,  512/32), tb32>>>(proj_w, p_wp,  512, 512);
    k_wt<<<dim3(512/32, 2048/32), tb32>>>(fc1_w,  p_wf1, 2048, 512);
    k_wt<<<dim3(2048/32, 512/32), tb32>>>(fc2_w,  p_wf2,  512, 2048);

    // 1) fused lif(x) + depthwise conv + residual
    k_convf<<<Bb*C, 256>>>(x, conv_w, conv_b, lifw, p_xc);
    // 2) [C,HW] -> [N,C] token layout
    k_tr<<<dim3(Nn/32, C/32, TB), tb32>>>(p_xc, p_xt, C, Nn);
    // 3) fused LN1 + LIF + qkv gather + q/k/v LIF
    k_qkv<<<BN, 512>>>(ln1_g, ln1_b, lifw, p_xt, p_qkvs);
    // 4) exact integer linear attention
    k_attn<<<T*Bb*NH, 256>>>(p_qkvs, p_attn);
    // 5) fused attn LIF + proj + residual
    k_projf<<<BN, 512>>>(lifw, proj_b, p_attn, p_xt);
    // 6) fused LN2 + MLP + residual
    k_mlp<<<BN, 512>>>(lifw, ln2_g, ln2_b, fc1_b, fc2_b, p_xt);
    // 7) [N,C] -> [C,HW] output layout
    k_tr<<<dim3(C/32, Nn/32, TB), tb32>>>(p_xt, out, Nn, C);
}

// round 11
// speedup vs baseline: 1.7085x; 1.1243x over previous
#include <cuda_runtime.h>
#include <cuda_bf16.h>
#include <cuda_fp8.h>
#include <math.h>

#define T  4
#define Bb 16
#define C  512
#define HW 256
#define Nn 256
#define C3 1536
#define HID 2048
#define NH 8
#define Dd 64
#define TB (T*Bb)            // 64
#define BN (Bb*Nn)           // 4096
#define TBN (T*Bb*Nn)        // 16384
#define XSZ (T*Bb*C*HW)      // 8388608

// ---------------- scratch (no cudaMalloc allowed) ----------------
__device__ float         g_xc[XSZ];       // x + pos         [T,B,C,HW]
__device__ float         g_xt[XSZ];       // residual stream [T,B,N,C]
__device__ unsigned char g_qkvs[TBN*C3];  // q/k/v spikes    [T,B,N,3C]
__device__ float         g_attn[XSZ];     // attn out        [T,B,N,C]
__device__ __align__(16) unsigned char g_wq8 [C*C3];   // fp8 [cin][3C]
__device__ __align__(16) unsigned char g_wf18[C*HID];  // fp8 [cin][HID]
__device__ __align__(16) __nv_bfloat16 g_wp [C*C];     // bf16 [cin][C]
__device__ __align__(16) __nv_bfloat16 g_wf2[HID*C];   // bf16 [hid][C]

__device__ __forceinline__ float sigm(float w){ return 1.f/(1.f+expf(-w)); }

__device__ __forceinline__ float4 fp8x4_to_f4(unsigned u){
    __half2_raw h0 = __nv_cvt_fp8x2_to_halfraw2((__nv_fp8x2_storage_t)(u & 0xFFFFu), __NV_E4M3);
    __half2_raw h1 = __nv_cvt_fp8x2_to_halfraw2((__nv_fp8x2_storage_t)(u >> 16),     __NV_E4M3);
    __half2 a = *reinterpret_cast<__half2*>(&h0);
    __half2 b = *reinterpret_cast<__half2*>(&h1);
    float2 fa = __half22float2(a), fb = __half22float2(b);
    return make_float4(fa.x, fa.y, fb.x, fb.y);
}

// ---------- single kernel: all 4 weight transposes (fp32 -> fp8/bf16) ----
__global__ void k_wt_all(const float* __restrict__ qkv_w, const float* __restrict__ proj_w,
                         const float* __restrict__ fc1_w, const float* __restrict__ fc2_w){
    __shared__ float tile[32][33];
    int bid = blockIdx.x;
    const float* src;  int nR, nC, local, mode;
    if      (bid < 768) { src = qkv_w;  nR = 1536; nC = 512;  local = bid;        mode = 0; }
    else if (bid < 1024){ src = proj_w; nR = 512;  nC = 512;  local = bid - 768;  mode = 1; }
    else if (bid < 2048){ src = fc1_w;  nR = 2048; nC = 512;  local = bid - 1024; mode = 2; }
    else                { src = fc2_w;  nR = 512;  nC = 2048; local = bid - 2048; mode = 3; }
    int tpr = nC >> 5;
    int tx = local % tpr, ty = local / tpr;
    int cx = tx*32 + threadIdx.x;
    int ry = ty*32 + threadIdx.y;
    tile[threadIdx.y][threadIdx.x] = src[(size_t)ry*nC + cx];
    __syncthreads();
    int ox = ty*32 + threadIdx.x;   // within nR
    int oy = tx*32 + threadIdx.y;   // within nC
    float v = tile[threadIdx.x][threadIdx.y];
    size_t di = (size_t)oy*nR + ox;
    if      (mode == 0) g_wq8 [di] = __nv_cvt_float_to_fp8(v, __NV_SATFINITE, __NV_E4M3);
    else if (mode == 1) g_wp  [di] = __float2bfloat16(v);
    else if (mode == 2) g_wf18[di] = __nv_cvt_float_to_fp8(v, __NV_SATFINITE, __NV_E4M3);
    else                g_wf2 [di] = __float2bfloat16(v);
}

// ---------- fused lif(x) + depthwise 3x3 conv + residual -----------------
__global__ void k_convf(const float* __restrict__ x, const float* __restrict__ conv_w,
                        const float* __restrict__ conv_b, const float* __restrict__ lifw,
                        float* __restrict__ xc){
    __shared__ float xs[T][324];
    __shared__ unsigned char ss[T][324];
    int bc = blockIdx.x;  int b = bc >> 9;  int c = bc & 511;
    int tid = threadIdx.x;
    float decay = sigm(lifw[0]);
    for (int i = tid; i < 324; i += 256){
        int y = i/18 - 1, xx = i%18 - 1;
        bool in = (y>=0 && y<16 && xx>=0 && xx<16);
        int p = y*16 + xx;
        #pragma unroll
        for (int t=0; t<T; t++)
            xs[t][i] = in ? x[((size_t)(t*Bb+b)*C + c)*HW + p] : 0.f;
    }
    __syncthreads();
    for (int i = tid; i < 324; i += 256){
        float v = 0.f;
        #pragma unroll
        for (int t=0; t<T; t++){
            float xv = xs[t][i];
            v = v + (xv - v)*decay;
            unsigned char s = (v >= 1.0f);
            if (s) v = 0.f;
            ss[t][i] = s;
        }
    }
    __syncthreads();
    int py = tid >> 4, px = tid & 15;
    float w[9];
    #pragma unroll
    for (int j=0;j<9;j++) w[j] = conv_w[c*9 + j];
    float cb = conv_b[c];
    #pragma unroll
    for (int t=0; t<T; t++){
        float acc = 0.f;
        #pragma unroll
        for (int ky=0; ky<3; ky++)
            #pragma unroll
            for (int kx=0; kx<3; kx++)
                acc += (float)ss[t][(py+ky)*18 + px+kx] * w[ky*3+kx];
        xc[((size_t)(t*Bb+b)*C + c)*HW + tid] = xs[t][(py+1)*18 + px+1] + acc + cb;
    }
}

// ---------- batched 2D fp32 transpose (per z-slice) ----------------------
__global__ void k_tr(const float* __restrict__ src, float* __restrict__ dst,
                     int rows, int cols){
    __shared__ float tile[32][33];
    int z = blockIdx.z;
    const float* s = src + (size_t)z*rows*cols;
    float*       d = dst + (size_t)z*rows*cols;
    int xx = blockIdx.x*32 + threadIdx.x;
    int yy = blockIdx.y*32 + threadIdx.y;
    tile[threadIdx.y][threadIdx.x] = s[(size_t)yy*cols + xx];
    __syncthreads();
    int x2 = blockIdx.y*32 + threadIdx.x;
    int y2 = blockIdx.x*32 + threadIdx.y;
    d[(size_t)y2*rows + x2] = tile[threadIdx.x][threadIdx.y];
}

// ---------- block-wide sum over 512 threads ------------------------------
__device__ __forceinline__ float bsum(float v, float* red){
    #pragma unroll
    for (int off=16; off; off>>=1) v += __shfl_down_sync(0xffffffffu, v, off);
    int lane = threadIdx.x & 31, w = threadIdx.x >> 5;
    if (lane==0) red[w] = v;
    __syncthreads();
    if (w==0){
        float s = (lane < 16) ? red[lane] : 0.f;
        #pragma unroll
        for (int off=8; off; off>>=1) s += __shfl_down_sync(0xffffffffu, s, off);
        if (lane==0) red[16] = s;
    }
    __syncthreads();
    float r = red[16];
    __syncthreads();
    return r;
}

// warp-0 builds ordered active-channel list from 16-word mask -------------
__device__ __forceinline__ void build_list(const unsigned* mask, int* list, int* s_cnt){
    int tid = threadIdx.x;
    if (tid < 32){
        unsigned wv = (tid < 16) ? mask[tid] : 0u;
        int c = __popc(wv);
        int inc = c;
        #pragma unroll
        for (int off=1; off<32; off<<=1){
            int v = __shfl_up_sync(0xffffffffu, inc, off);
            if (tid >= off) inc += v;
        }
        int idx = inc - c;
        while (wv){ int b = __ffs(wv)-1; wv &= wv-1; list[idx++] = (tid<<5) + b; }
        if (tid == 31) *s_cnt = inc;
    }
    __syncthreads();
}

// ---------- fused LN1 + LIF + qkv gather (fp8) + q/k/v LIF ---------------
__global__ void __launch_bounds__(512) k_qkv(
        const float* __restrict__ ln1_g, const float* __restrict__ ln1_b,
        const float* __restrict__ lifw,  const float* __restrict__ xt,
        unsigned char* __restrict__ qkvs){
    __shared__ unsigned mask[16];
    __shared__ int list[512];
    __shared__ int s_cnt;
    __shared__ float red[17];
    int bn = blockIdx.x;  int b = bn >> 8;  int n = bn & 255;
    int tid = threadIdx.x;
    float gg = ln1_g[tid], be = ln1_b[tid];
    float d1 = sigm(lifw[1]);
    float dq = sigm(lifw[2 + ((tid < 384) ? (tid >> 7) : 0)]);
    float vln = 0.f;
    float v0=0.f, v1=0.f, v2=0.f, v3=0.f;
    for (int t=0; t<T; t++){
        int tok = (t*Bb + b)*Nn + n;
        float xv = xt[(size_t)tok*C + tid];
        float m  = bsum(xv, red) * (1.f/512.f);
        float d  = xv - m;
        float var = bsum(d*d, red) * (1.f/512.f);
        float y = d * (1.f/sqrtf(var + 1e-5f)) * gg + be;
        vln = vln + (y - vln)*d1;
        int s = (vln >= 1.0f); if (s) vln = 0.f;
        unsigned bm = __ballot_sync(0xffffffffu, s);
        if ((tid & 31) == 0) mask[tid >> 5] = bm;
        __syncthreads();
        build_list(mask, list, &s_cnt);
        if (tid < 384){
            const unsigned char* wb = g_wq8 + (tid << 2);
            float a0=0.f, a1=0.f, a2=0.f, a3=0.f;
            int cnt = s_cnt, i = 0;
            for (; i + 4 <= cnt; i += 4){
                unsigned u0 = *(const unsigned*)(wb + (size_t)list[i  ]*C3);
                unsigned u1 = *(const unsigned*)(wb + (size_t)list[i+1]*C3);
                unsigned u2 = *(const unsigned*)(wb + (size_t)list[i+2]*C3);
                unsigned u3 = *(const unsigned*)(wb + (size_t)list[i+3]*C3);
                float4 f0 = fp8x4_to_f4(u0), f1 = fp8x4_to_f4(u1);
                float4 f2 = fp8x4_to_f4(u2), f3 = fp8x4_to_f4(u3);
                a0 += f0.x; a1 += f0.y; a2 += f0.z; a3 += f0.w;
                a0 += f1.x; a1 += f1.y; a2 += f1.z; a3 += f1.w;
                a0 += f2.x; a1 += f2.y; a2 += f2.z; a3 += f2.w;
                a0 += f3.x; a1 += f3.y; a2 += f3.z; a3 += f3.w;
            }
            for (; i < cnt; i++){
                unsigned u = *(const unsigned*)(wb + (size_t)list[i]*C3);
                float4 f = fp8x4_to_f4(u);
                a0 += f.x; a1 += f.y; a2 += f.z; a3 += f.w;
            }
            v0 = v0 + (a0 - v0)*dq;  v1 = v1 + (a1 - v1)*dq;
            v2 = v2 + (a2 - v2)*dq;  v3 = v3 + (a3 - v3)*dq;
            uchar4 sc;
            sc.x = (v0 >= 1.0f); if (sc.x) v0 = 0.f;
            sc.y = (v1 >= 1.0f); if (sc.y) v1 = 0.f;
            sc.z = (v2 >= 1.0f); if (sc.z) v2 = 0.f;
            sc.w = (v3 >= 1.0f); if (sc.w) v3 = 0.f;
            *reinterpret_cast<uchar4*>(qkvs + (size_t)tok*C3 + (tid<<2)) = sc;
        }
        __syncthreads();
    }
}

// ---------- exact integer linear attention (smem-staged loads) -----------
__global__ void k_attn(const unsigned char* __restrict__ qkvs, float* __restrict__ attn){
    __shared__ int4 stage[1024];            // 256 tokens x 64B
    __shared__ unsigned kcol[Dd][8];
    __shared__ unsigned vcol[Dd][8];
    __shared__ int kvs[Dd*Dd];
    int bx = blockIdx.x;
    int hd = bx & 7;  int b = (bx >> 3) & 15;  int t = bx >> 7;
    int tid = threadIdx.x;
    int tbase = (t*Bb + b)*Nn;
    const unsigned char* base = qkvs + (size_t)tbase*C3;
    const unsigned char* sb = (const unsigned char*)stage;
    int koff = C + hd*Dd, voff = 2*C + hd*Dd, qoff = hd*Dd;

    for (int i=tid; i<1024; i+=256){
        int nn = i >> 2, ch = i & 3;
        stage[i] = *reinterpret_cast<const int4*>(base + (size_t)nn*C3 + koff + ch*16);
    }
    __syncthreads();
    for (int s=tid; s<512; s+=256){
        int e = s >> 3, w = s & 7;
        unsigned kb = 0;
        #pragma unroll 4
        for (int i=0;i<32;i++) kb |= ((unsigned)(sb[(w*32+i)*64 + e] != 0)) << i;
        kcol[e][w] = kb;
    }
    __syncthreads();
    for (int i=tid; i<1024; i+=256){
        int nn = i >> 2, ch = i & 3;
        stage[i] = *reinterpret_cast<const int4*>(base + (size_t)nn*C3 + voff + ch*16);
    }
    __syncthreads();
    for (int s=tid; s<512; s+=256){
        int e = s >> 3, w = s & 7;
        unsigned vb = 0;
        #pragma unroll 4
        for (int i=0;i<32;i++) vb |= ((unsigned)(sb[(w*32+i)*64 + e] != 0)) << i;
        vcol[e][w] = vb;
    }
    __syncthreads();
    for (int s=tid; s<Dd*Dd; s+=256){
        int e = s >> 6, f = s & 63;
        int sum = 0;
        #pragma unroll
        for (int w=0; w<8; w++) sum += __popc(kcol[e][w] & vcol[f][w]);
        kvs[s] = sum;
    }
    __syncthreads();
    for (int i=tid; i<1024; i+=256){
        int nn = i >> 2, ch = i & 3;
        stage[i] = *reinterpret_cast<const int4*>(base + (size_t)nn*C3 + qoff + ch*16);
    }
    __syncthreads();
    int n = tid;
    unsigned qb0=0, qb1=0;
    #pragma unroll 4
    for (int i=0;i<32;i++){
        qb0 |= ((unsigned)(sb[n*64 + i]      != 0)) << i;
        qb1 |= ((unsigned)(sb[n*64 + 32 + i] != 0)) << i;
    }
    int acc[Dd];
    #pragma unroll
    for (int f=0; f<Dd; f++) acc[f] = 0;
    unsigned m = qb0;
    while (m){
        int e = __ffs(m) - 1;  m &= m - 1;
        const int* kr = kvs + e*Dd;
        #pragma unroll
        for (int f=0; f<Dd; f++) acc[f] += kr[f];
    }
    m = qb1;
    while (m){
        int e = __ffs(m) + 31;  m &= m - 1;
        const int* kr = kvs + e*Dd;
        #pragma unroll
        for (int f=0; f<Dd; f++) acc[f] += kr[f];
    }
    float* outp = attn + (size_t)(tbase + n)*C + hd*Dd;
    #pragma unroll
    for (int f=0; f<Dd; f++) outp[f] = (float)acc[f] * 0.125f;
}

// ---------- fused tail: attnLIF+proj+res + LN2+LIF+fc1+hidLIF+fc2+res ----
__global__ void __launch_bounds__(512) k_tail(
        const float* __restrict__ lifw, const float* __restrict__ proj_b,
        const float* __restrict__ ln2_g, const float* __restrict__ ln2_b,
        const float* __restrict__ fc1_b, const float* __restrict__ fc2_b,
        const float* __restrict__ attn, float* __restrict__ xt){
    __shared__ unsigned mask[16];
    __shared__ unsigned mask2[64];
    __shared__ int list[512];
    __shared__ int s_cnt;
    __shared__ float red[17];
    int bn = blockIdx.x;  int b = bn >> 8;  int n = bn & 255;
    int tid = threadIdx.x;
    int lane = tid & 31, wrp = tid >> 5;
    float pb = proj_b[tid];
    float gg = ln2_g[tid], be = ln2_b[tid];
    float fb0 = fc1_b[tid*4], fb1 = fc1_b[tid*4+1], fb2 = fc1_b[tid*4+2], fb3 = fc1_b[tid*4+3];
    float f2b = fc2_b[tid];
    float d5 = sigm(lifw[5]), d6 = sigm(lifw[6]), d7 = sigm(lifw[7]);
    float v5 = 0.f, vln = 0.f;
    float h0=0.f, h1=0.f, h2=0.f, h3=0.f;
    for (int t=0; t<T; t++){
        int tok = (t*Bb + b)*Nn + n;
        // --- attn LIF + proj gather + residual ---
        float av = attn[(size_t)tok*C + tid];
        v5 = v5 + (av - v5)*d5;
        int s5 = (v5 >= 1.0f); if (s5) v5 = 0.f;
        unsigned bm = __ballot_sync(0xffffffffu, s5);
        if (lane == 0) mask[wrp] = bm;
        __syncthreads();
        build_list(mask, list, &s_cnt);
        float xv = xt[(size_t)tok*C + tid];
        {
            int cnt = s_cnt;
            for (int i=0; i<cnt; i++)
                xv += __bfloat162float(g_wp[(size_t)list[i]*C + tid]);
        }
        xv += pb;
        __syncthreads();
        // --- LN2 + LIF ---
        float m  = bsum(xv, red) * (1.f/512.f);
        float d  = xv - m;
        float var = bsum(d*d, red) * (1.f/512.f);
        float y = d * (1.f/sqrtf(var + 1e-5f)) * gg + be;
        vln = vln + (y - vln)*d6;
        int s6 = (vln >= 1.0f); if (s6) vln = 0.f;
        bm = __ballot_sync(0xffffffffu, s6);
        if (lane == 0) mask[wrp] = bm;
        __syncthreads();
        build_list(mask, list, &s_cnt);
        // --- fc1 gather (fp8) ---
        float a0=0.f, a1=0.f, a2=0.f, a3=0.f;
        {
            const unsigned char* wb = g_wf18 + (tid << 2);
            int cnt = s_cnt, i = 0;
            for (; i + 4 <= cnt; i += 4){
                unsigned u0 = *(const unsigned*)(wb + (size_t)list[i  ]*HID);
                unsigned u1 = *(const unsigned*)(wb + (size_t)list[i+1]*HID);
                unsigned u2 = *(const unsigned*)(wb + (size_t)list[i+2]*HID);
                unsigned u3 = *(const unsigned*)(wb + (size_t)list[i+3]*HID);
                float4 f0 = fp8x4_to_f4(u0), f1 = fp8x4_to_f4(u1);
                float4 f2 = fp8x4_to_f4(u2), f3 = fp8x4_to_f4(u3);
                a0 += f0.x; a1 += f0.y; a2 += f0.z; a3 += f0.w;
                a0 += f1.x; a1 += f1.y; a2 += f1.z; a3 += f1.w;
                a0 += f2.x; a1 += f2.y; a2 += f2.z; a3 += f2.w;
                a0 += f3.x; a1 += f3.y; a2 += f3.z; a3 += f3.w;
            }
            for (; i < cnt; i++){
                unsigned u = *(const unsigned*)(wb + (size_t)list[i]*HID);
                float4 f = fp8x4_to_f4(u);
                a0 += f.x; a1 += f.y; a2 += f.z; a3 += f.w;
            }
        }
        a0 += fb0; a1 += fb1; a2 += fb2; a3 += fb3;
        // --- hidden LIF ---
        h0 = h0 + (a0 - h0)*d7;  h1 = h1 + (a1 - h1)*d7;
        h2 = h2 + (a2 - h2)*d7;  h3 = h3 + (a3 - h3)*d7;
        int t0 = (h0 >= 1.0f); if (t0) h0 = 0.f;
        int t1 = (h1 >= 1.0f); if (t1) h1 = 0.f;
        int t2 = (h2 >= 1.0f); if (t2) h2 = 0.f;
        int t3 = (h3 >= 1.0f); if (t3) h3 = 0.f;
        // hidden spikes -> mask2 via 16-warp parallel ballots
        unsigned b0 = __ballot_sync(0xffffffffu, t0);
        unsigned b1 = __ballot_sync(0xffffffffu, t1);
        unsigned b2 = __ballot_sync(0xffffffffu, t2);
        unsigned b3 = __ballot_sync(0xffffffffu, t3);
        if (lane == 0){
            mask2[wrp*4 + 0] = b0;  mask2[wrp*4 + 1] = b1;
            mask2[wrp*4 + 2] = b2;  mask2[wrp*4 + 3] = b3;
        }
        __syncthreads();
        // --- fc2 gather (bf16) + residual, write final row ---
        float o = 0.f;
        for (int w64 = 0; w64 < 64; w64++){
            unsigned mv = mask2[w64];
            int ww = w64 >> 2, bb = w64 & 3;
            while (mv){
                int i = __ffs(mv) - 1;  mv &= mv - 1;
                int j = ww*128 + i*4 + bb;      // hidden index
                o += __bfloat162float(g_wf2[(size_t)j*C + tid]);
            }
        }
        xt[(size_t)tok*C + tid] = xv + o + f2b;
        __syncthreads();
    }
}

// ------------------------------- launch ----------------------------------
extern "C" void kernel_launch(void* const* d_in, const int* in_sizes, int n_in,
                              void* d_out, int out_size){
    const float* x      = (const float*)d_in[0];
    const float* conv_w = (const float*)d_in[1];
    const float* conv_b = (const float*)d_in[2];
    const float* ln1_g  = (const float*)d_in[3];
    const float* ln1_b  = (const float*)d_in[4];
    const float* qkv_w  = (const float*)d_in[5];
    const float* proj_w = (const float*)d_in[6];
    const float* proj_b = (const float*)d_in[7];
    const float* ln2_g  = (const float*)d_in[8];
    const float* ln2_b  = (const float*)d_in[9];
    const float* fc1_w  = (const float*)d_in[10];
    const float* fc1_b  = (const float*)d_in[11];
    const float* fc2_w  = (const float*)d_in[12];
    const float* fc2_b  = (const float*)d_in[13];
    const float* lifw   = (const float*)d_in[14];
    float* out = (float*)d_out;

    float *p_xc, *p_xt, *p_attn;
    unsigned char* p_qkvs;
    cudaGetSymbolAddress((void**)&p_xc,   g_xc);
    cudaGetSymbolAddress((void**)&p_xt,   g_xt);
    cudaGetSymbolAddress((void**)&p_attn, g_attn);
    cudaGetSymbolAddress((void**)&p_qkvs, g_qkvs);

    dim3 tb32(32,32);
    // 0) all weight transposes in one launch
    k_wt_all<<<3072, tb32>>>(qkv_w, proj_w, fc1_w, fc2_w);
    // 1) fused lif(x) + depthwise conv + residual
    k_convf<<<Bb*C, 256>>>(x, conv_w, conv_b, lifw, p_xc);
    // 2) [C,HW] -> [N,C] token layout
    k_tr<<<dim3(Nn/32, C/32, TB), tb32>>>(p_xc, p_xt, C, Nn);
    // 3) fused LN1 + LIF + qkv gather (fp8) + q/k/v LIF
    k_qkv<<<BN, 512>>>(ln1_g, ln1_b, lifw, p_xt, p_qkvs);
    // 4) exact integer linear attention
    k_attn<<<T*Bb*NH, 256>>>(p_qkvs, p_attn);
    // 5) fused tail: attn LIF + proj + residual + LN2 + MLP + residual
    k_tail<<<BN, 512>>>(lifw, proj_b, ln2_g, ln2_b, fc1_b, fc2_b, p_attn, p_xt);
    // 6) [N,C] -> [C,HW] output layout
    k_tr<<<dim3(C/32, Nn/32, TB), tb32>>>(p_xt, out, Nn, C);
}